// round 12
// baseline (speedup 1.0000x reference)
#include <cuda_runtime.h>
#include <cuda_fp16.h>
#include <math.h>
#include <stdint.h>

// ---------------- constants ----------------
// B=2, S=2048, H=4096, NH=32, NKV=2, HD=128, ROT=64
// BS=4096 tokens; qkv width 4608 (q:[0,4096) k:[4096,4352) v:[4352,4608))

__device__ __half g_hid_h[(size_t)4096 * 4096];
__device__ __half g_wqkvT_h[(size_t)4608 * 4096];
__device__ __half g_wdenseT_h[(size_t)4096 * 4096];
__device__ __half g_q_h[(size_t)2 * 32 * 2048 * 128];  // [b][h][t][d] rope+scale
__device__ __half g_k_h[(size_t)2 * 2 * 2048 * 128];   // [b][kvh][t][d] rope
__device__ __half g_v_h[(size_t)4096 * 256];           // [tok][dglob]
__device__ __half g_attn_h[(size_t)4096 * 4096];       // [tok][H]

// ---------------- helpers ----------------
__device__ __forceinline__ uint32_t smem_u32(const void* p) {
    uint32_t a;
    asm("{ .reg .u64 t; cvta.to.shared.u64 t, %1; cvt.u32.u64 %0, t; }" : "=r"(a) : "l"(p));
    return a;
}
__device__ __forceinline__ void cp16(uint32_t s, const void* g) {
    asm volatile("cp.async.cg.shared.global [%0], [%1], 16;" :: "r"(s), "l"(g));
}
__device__ __forceinline__ void mma_f16(float* d, const uint32_t* a, const uint32_t* b) {
    asm volatile(
        "mma.sync.aligned.m16n8k16.row.col.f32.f16.f16.f32 "
        "{%0,%1,%2,%3}, {%4,%5,%6,%7}, {%8,%9}, {%0,%1,%2,%3};"
        : "+f"(d[0]), "+f"(d[1]), "+f"(d[2]), "+f"(d[3])
        : "r"(a[0]), "r"(a[1]), "r"(a[2]), "r"(a[3]), "r"(b[0]), "r"(b[1]));
}
__device__ __forceinline__ void ldsm4(uint32_t* r, uint32_t addr) {
    asm volatile("ldmatrix.sync.aligned.m8n8.x4.shared.b16 {%0,%1,%2,%3}, [%4];"
                 : "=r"(r[0]), "=r"(r[1]), "=r"(r[2]), "=r"(r[3]) : "r"(addr));
}
__device__ __forceinline__ void ldsm4t(uint32_t* r, uint32_t addr) {
    asm volatile("ldmatrix.sync.aligned.m8n8.x4.trans.shared.b16 {%0,%1,%2,%3}, [%4];"
                 : "=r"(r[0]), "=r"(r[1]), "=r"(r[2]), "=r"(r[3]) : "r"(addr));
}
__device__ __forceinline__ uint32_t packh2(float x, float y) {
    __half2 h = __floats2half2_rn(x, y);
    return *(uint32_t*)&h;
}

// ---------------- fp16 mma GEMM (ldmatrix, K-chunk 32) — LOCKED R6/R8 config ----
#define GS 3
#define STG_H 10240
#define STG_B (STG_H * 2)                 // 20480 bytes/stage
#define G_SMEM_BYTES (GS * STG_B)         // 61440

template <int MODE>
__global__ __launch_bounds__(256, 2)
void gemm_h_t(const __half* __restrict__ A, const __half* __restrict__ Bt,
              const float* __restrict__ bias, float* __restrict__ C,
              __half* __restrict__ qh, __half* __restrict__ kh, __half* __restrict__ vh,
              const int* __restrict__ positions, int M, int N, int K)
{
    extern __shared__ __half sh[];
    const uint32_t sb = smem_u32(sh);
    const int tid = threadIdx.x;
    const int wid = tid >> 5, lane = tid & 31;
    const int grp = lane >> 2, thr = lane & 3;
    const int wm = wid & 3, wn = wid >> 2;
    const int m0 = blockIdx.y * 128, n0 = blockIdx.x * 128;

    const int row = tid >> 1;
    const int off = (tid & 1) * 16;
    const __half* Ap = A + (size_t)(m0 + row) * K + off;
    const __half* Bp = Bt + (size_t)(n0 + row) * K + off;
    const uint32_t sA = sb + (uint32_t)(row * 40 + off) * 2;
    const uint32_t sB = sA + STG_H;

    auto load_stage = [&](int ch, int st) {
        const uint32_t so = (uint32_t)st * STG_B;
        const __half* a = Ap + ch * 32;
        const __half* b = Bp + ch * 32;
        cp16(sA + so, a);  cp16(sA + so + 16, a + 8);
        cp16(sB + so, b);  cp16(sB + so + 16, b + 8);
        asm volatile("cp.async.commit_group;" ::: "memory");
    };

    float acc[2][8][4];
#pragma unroll
    for (int mt = 0; mt < 2; mt++)
#pragma unroll
        for (int nt = 0; nt < 8; nt++)
#pragma unroll
            for (int j = 0; j < 4; j++) acc[mt][nt][j] = 0.f;

    const int NK = K >> 5;
    load_stage(0, 0);
    load_stage(1, 1);

    const int lrow = lane & 15;
    const int lcol = (lane >> 4) * 16;
    const uint32_t aAddr = sb + (uint32_t)((wm * 32 + lrow) * 40) * 2 + lcol;
    const uint32_t bAddr = sb + 10240 + (uint32_t)((wn * 64 + lrow) * 40) * 2 + lcol;

    int st = 0;
    for (int i = 0; i < NK; i++) {
        asm volatile("cp.async.wait_group %0;" :: "n"(1) : "memory");
        __syncthreads();
        int nxt = i + 2;
        if (nxt < NK) {
            int ns = st + 2; if (ns >= GS) ns -= GS;
            load_stage(nxt, ns);
        } else {
            asm volatile("cp.async.commit_group;" ::: "memory");
        }

        const uint32_t so = (uint32_t)st * STG_B;
#pragma unroll
        for (int kk = 0; kk < 2; kk++) {
            uint32_t a[2][4];
            ldsm4(a[0], aAddr + so + kk * 32);
            ldsm4(a[1], aAddr + so + 16 * 80 + kk * 32);
            uint32_t b[8][2];
#pragma unroll
            for (int ntp = 0; ntp < 4; ntp++) {
                uint32_t tt[4];
                ldsm4(tt, bAddr + so + ntp * (16 * 80) + kk * 32);
                b[2 * ntp][0] = tt[0];  b[2 * ntp][1] = tt[2];
                b[2 * ntp + 1][0] = tt[1];  b[2 * ntp + 1][1] = tt[3];
            }
#pragma unroll
            for (int mt = 0; mt < 2; mt++)
#pragma unroll
                for (int nt = 0; nt < 8; nt++)
                    mma_f16(acc[mt][nt], a[mt], b[nt]);
        }
        st++; if (st == GS) st = 0;
    }

    if (MODE == 0) {
#pragma unroll
        for (int mt = 0; mt < 2; mt++) {
            const int r0 = m0 + wm * 32 + mt * 16 + grp;
#pragma unroll
            for (int nt = 0; nt < 8; nt++) {
                const int col = n0 + wn * 64 + nt * 8 + thr * 2;
                float b0 = 0.f, b1 = 0.f;
                if (bias) { b0 = __ldg(&bias[col]); b1 = __ldg(&bias[col + 1]); }
                *(float2*)&C[(size_t)r0 * N + col] =
                    make_float2(acc[mt][nt][0] + b0, acc[mt][nt][1] + b1);
                *(float2*)&C[(size_t)(r0 + 8) * N + col] =
                    make_float2(acc[mt][nt][2] + b0, acc[mt][nt][3] + b1);
            }
        }
    } else {
        const int head = n0 >> 7;
#pragma unroll
        for (int mt = 0; mt < 2; mt++) {
            const int r0 = m0 + wm * 32 + mt * 16 + grp;
#pragma unroll
            for (int rs = 0; rs < 2; rs++) {
                const int r = r0 + rs * 8;
                const int t = r & 2047, bb = r >> 11;
                const float pos = (float)__ldg(&positions[r]);
#pragma unroll
                for (int nt = 0; nt < 8; nt++) {
                    const int col = n0 + wn * 64 + nt * 8 + thr * 2;
                    float v0 = acc[mt][nt][rs * 2] + __ldg(&bias[col]);
                    float v1 = acc[mt][nt][rs * 2 + 1] + __ldg(&bias[col + 1]);
                    const int d = col & 127;
                    if (head < 34) {
                        if (d < 64) {
                            const int pi = d >> 1;
                            float ang = pos * __expf((float)(-pi) * 0.28782313662425572f);
                            float c, s;
                            __sincosf(ang, &s, &c);
                            float o1 = v0 * c - v1 * s;
                            float o2 = v0 * s + v1 * c;
                            v0 = o1; v1 = o2;
                        }
                        if (head < 32) {
                            const float sc = 0.08838834764831845f;
                            uint32_t p = packh2(v0 * sc, v1 * sc);
                            *(uint32_t*)(qh + ((((size_t)(bb * 32 + head)) * 2048 + t) * 128 + d)) = p;
                        } else {
                            uint32_t p = packh2(v0, v1);
                            *(uint32_t*)(kh + ((((size_t)(bb * 2 + head - 32)) * 2048 + t) * 128 + d)) = p;
                        }
                    } else {
                        uint32_t p = packh2(v0, v1);
                        *(uint32_t*)(vh + ((size_t)r * 256 + (col - 4352))) = p;
                    }
                }
            }
        }
    }
}

// ---------------- prep kernels ----------------
__global__ void convert_h_kernel(const float4* __restrict__ src, uint2* __restrict__ dst, int n4)
{
    int i = blockIdx.x * blockDim.x + threadIdx.x;
    if (i >= n4) return;
    float4 v = src[i];
    uint2 o;
    o.x = packh2(v.x, v.y);
    o.y = packh2(v.z, v.w);
    dst[i] = o;
}

__global__ void transpose_h_kernel(const float* __restrict__ src, __half* __restrict__ dst,
                                   int R, int C)
{
    __shared__ float t[32][33];
    int c0 = blockIdx.x * 32, r0 = blockIdx.y * 32;
    int x = threadIdx.x, y = threadIdx.y;
#pragma unroll
    for (int i = 0; i < 32; i += 8)
        t[y + i][x] = src[(size_t)(r0 + y + i) * C + c0 + x];
    __syncthreads();
#pragma unroll
    for (int i = 0; i < 32; i += 8)
        dst[(size_t)(c0 + y + i) * R + r0 + x] = __float2half(t[x][y + i]);
}

// ---------------- fp16 mma flash attention (64-row CTA, 4 warps, 2 CTAs/SM) ----
// smem halves: Qs[64][136], Ks[2][64][136], Vs[2][64][136] (token-major V)
#define AQ_ST 136
#define AK_ST 136
#define SQ_OFF 0
#define SK_OFF (64 * AQ_ST)                       // 8704
#define SV_OFF (SK_OFF + 2 * 64 * AK_ST)          // 26112
#define A_SMEM_HALVES (SV_OFF + 2 * 64 * AK_ST)   // 43520
#define A_SMEM_BYTES (A_SMEM_HALVES * 2)          // 87040

__global__ __launch_bounds__(128, 2)
void attn_mma_kernel(const __half* __restrict__ qh, const __half* __restrict__ kh,
                     const __half* __restrict__ vh, __half* __restrict__ out)
{
    extern __shared__ __half sa[];
    const uint32_t sb = smem_u32(sa);
    const int tid = threadIdx.x;
    const int w = tid >> 5, lane = tid & 31;      // w: 0..3
    const int grp = lane >> 2, thr = lane & 3;
    const int qt = 31 - blockIdx.x;               // 64-row q tiles, big first
    const int h = blockIdx.y, b = blockIdx.z;
    const int kvh = h >> 4;

    const __half* Qg = qh + (((size_t)(b * 32 + h)) * 2048 + qt * 64) * 128;
    const __half* Kg = kh + ((size_t)(b * 2 + kvh)) * 2048 * 128;
    const __half* Vg = vh + (size_t)(b * 2048) * 256 + kvh * 128;

    // Q load: 64 rows x 128 halves; 2 thr/row, 8 cp16 each.
    {
        int r = tid >> 1;
        int hf = (tid & 1) * 64;   // halves
        const __half* src = Qg + r * 128 + hf;
        uint32_t dst = sb + (uint32_t)(SQ_OFF + r * AQ_ST + hf) * 2;
#pragma unroll
        for (int j = 0; j < 8; j++) cp16(dst + j * 16, src + j * 8);
    }
    auto load_kv = [&](int kt, int buf) {
        int r = tid >> 1;
        int hf = (tid & 1) * 64;
        {
            const __half* src = Kg + ((size_t)(kt * 64 + r)) * 128 + hf;
            uint32_t dst = sb + (uint32_t)(SK_OFF + buf * 64 * AK_ST + r * AK_ST + hf) * 2;
#pragma unroll
            for (int j = 0; j < 8; j++) cp16(dst + j * 16, src + j * 8);
        }
        {
            const __half* src = Vg + ((size_t)(kt * 64 + r)) * 256 + hf;
            uint32_t dst = sb + (uint32_t)(SV_OFF + buf * 64 * AK_ST + r * AK_ST + hf) * 2;
#pragma unroll
            for (int j = 0; j < 8; j++) cp16(dst + j * 16, src + j * 8);
        }
    };

    const int NT = qt + 1;
    load_kv(0, 0);
    asm volatile("cp.async.commit_group;" ::: "memory");

    float o[16][4];
#pragma unroll
    for (int nt = 0; nt < 16; nt++)
#pragma unroll
        for (int j = 0; j < 4; j++) o[nt][j] = 0.f;
    float m1 = -1e30f, m2 = -1e30f, l1 = 0.f, l2 = 0.f;

    const int qr1 = qt * 64 + w * 16 + grp;
    const int qr2 = qr1 + 8;

    const int lrow = lane & 15;
    const int lcol = (lane >> 4) * 16;
    const uint32_t qAddr = sb + (uint32_t)(SQ_OFF + (w * 16 + lrow) * AQ_ST) * 2 + lcol;
    const uint32_t kAddr0 = sb + (uint32_t)(SK_OFF + lrow * AK_ST) * 2 + lcol;
    const uint32_t vAddr0 = sb + (uint32_t)(SV_OFF + lrow * AK_ST + (lane >> 4) * 8) * 2;

    for (int kt = 0; kt < NT; kt++) {
        if (kt + 1 < NT) load_kv(kt + 1, (kt + 1) & 1);
        asm volatile("cp.async.commit_group;" ::: "memory");
        asm volatile("cp.async.wait_group 1;" ::: "memory");
        __syncthreads();

        {
            const uint32_t kA = kAddr0 + (uint32_t)((kt & 1) * 64 * AK_ST) * 2;
            const uint32_t vA = vAddr0 + (uint32_t)((kt & 1) * 64 * AK_ST) * 2;

            float sc[8][4];
#pragma unroll
            for (int nt = 0; nt < 8; nt++)
#pragma unroll
                for (int j = 0; j < 4; j++) sc[nt][j] = 0.f;

#pragma unroll
            for (int kk = 0; kk < 8; kk++) {
                uint32_t aq[4];
                ldsm4(aq, qAddr + kk * 32);
#pragma unroll
                for (int ntp = 0; ntp < 4; ntp++) {
                    uint32_t tt[4];
                    ldsm4(tt, kA + ntp * (16 * AK_ST * 2) + kk * 32);
                    uint32_t b0[2] = {tt[0], tt[2]};
                    uint32_t b1[2] = {tt[1], tt[3]};
                    mma_f16(sc[2 * ntp], aq, b0);
                    mma_f16(sc[2 * ntp + 1], aq, b1);
                }
            }

            // causal mask: only the diagonal tile needs it
            if (kt * 64 + 63 > qt * 64 + w * 16) {
#pragma unroll
                for (int nt = 0; nt < 8; nt++) {
                    int c0 = kt * 64 + nt * 8 + thr * 2;
                    if (c0 > qr1) sc[nt][0] = -1e30f;
                    if (c0 + 1 > qr1) sc[nt][1] = -1e30f;
                    if (c0 > qr2) sc[nt][2] = -1e30f;
                    if (c0 + 1 > qr2) sc[nt][3] = -1e30f;
                }
            }

            float rm1 = -1e30f, rm2 = -1e30f;
#pragma unroll
            for (int nt = 0; nt < 8; nt++) {
                rm1 = fmaxf(rm1, fmaxf(sc[nt][0], sc[nt][1]));
                rm2 = fmaxf(rm2, fmaxf(sc[nt][2], sc[nt][3]));
            }
            rm1 = fmaxf(rm1, __shfl_xor_sync(0xffffffffu, rm1, 1));
            rm1 = fmaxf(rm1, __shfl_xor_sync(0xffffffffu, rm1, 2));
            rm2 = fmaxf(rm2, __shfl_xor_sync(0xffffffffu, rm2, 1));
            rm2 = fmaxf(rm2, __shfl_xor_sync(0xffffffffu, rm2, 2));

            float mn1 = fmaxf(m1, rm1), mn2 = fmaxf(m2, rm2);
            float f1 = __expf(m1 - mn1), f2 = __expf(m2 - mn2);
            m1 = mn1; m2 = mn2;

            uint32_t pf[8][2];
            float s1 = 0.f, s2 = 0.f;
#pragma unroll
            for (int nt = 0; nt < 8; nt++) {
                float e0 = __expf(sc[nt][0] - mn1);
                float e1 = __expf(sc[nt][1] - mn1);
                float e2 = __expf(sc[nt][2] - mn2);
                float e3 = __expf(sc[nt][3] - mn2);
                s1 += e0 + e1; s2 += e2 + e3;
                pf[nt][0] = packh2(e0, e1);
                pf[nt][1] = packh2(e2, e3);
            }
            l1 = l1 * f1 + s1;
            l2 = l2 * f2 + s2;

#pragma unroll
            for (int nt = 0; nt < 16; nt++) {
                o[nt][0] *= f1; o[nt][1] *= f1;
                o[nt][2] *= f2; o[nt][3] *= f2;
            }

#pragma unroll
            for (int kk = 0; kk < 4; kk++) {
                uint32_t ap[4] = {pf[2 * kk][0], pf[2 * kk][1],
                                  pf[2 * kk + 1][0], pf[2 * kk + 1][1]};
                const uint32_t vk = vA + (uint32_t)(kk * 16 * AK_ST) * 2;
#pragma unroll
                for (int ntdp = 0; ntdp < 8; ntdp++) {
                    uint32_t tt[4];
                    ldsm4t(tt, vk + ntdp * 32);
                    uint32_t b0[2] = {tt[0], tt[1]};
                    uint32_t b1[2] = {tt[2], tt[3]};
                    mma_f16(o[2 * ntdp], ap, b0);
                    mma_f16(o[2 * ntdp + 1], ap, b1);
                }
            }
        }
        __syncthreads();
    }

    l1 += __shfl_xor_sync(0xffffffffu, l1, 1);
    l1 += __shfl_xor_sync(0xffffffffu, l1, 2);
    l2 += __shfl_xor_sync(0xffffffffu, l2, 1);
    l2 += __shfl_xor_sync(0xffffffffu, l2, 2);
    float inv1 = 1.f / l1, inv2 = 1.f / l2;

    const int row1 = b * 2048 + qr1;
    const int row2 = b * 2048 + qr2;
#pragma unroll
    for (int ntd = 0; ntd < 16; ntd++) {
        int col = h * 128 + ntd * 8 + thr * 2;
        *(uint32_t*)(out + (size_t)row1 * 4096 + col) = packh2(o[ntd][0] * inv1, o[ntd][1] * inv1);
        *(uint32_t*)(out + (size_t)row2 * 4096 + col) = packh2(o[ntd][2] * inv2, o[ntd][3] * inv2);
    }
}

// ---------------- launch ----------------
extern "C" void kernel_launch(void* const* d_in, const int* in_sizes, int n_in,
                              void* d_out, int out_size)
{
    const float* hidden    = (const float*)d_in[0];
    const float* w_qkv     = (const float*)d_in[1];
    const float* b_qkv     = (const float*)d_in[2];
    const float* w_dense   = (const float*)d_in[3];
    const int*   positions = (const int*)d_in[4];
    float* out = (float*)d_out;

    __half *hid_h, *wqkvT_h, *wdenseT_h, *q_h, *k_h, *v_h, *attn_h;
    cudaGetSymbolAddress((void**)&hid_h, g_hid_h);
    cudaGetSymbolAddress((void**)&wqkvT_h, g_wqkvT_h);
    cudaGetSymbolAddress((void**)&wdenseT_h, g_wdenseT_h);
    cudaGetSymbolAddress((void**)&q_h, g_q_h);
    cudaGetSymbolAddress((void**)&k_h, g_k_h);
    cudaGetSymbolAddress((void**)&v_h, g_v_h);
    cudaGetSymbolAddress((void**)&attn_h, g_attn_h);

    cudaFuncSetAttribute(gemm_h_t<0>, cudaFuncAttributeMaxDynamicSharedMemorySize, G_SMEM_BYTES);
    cudaFuncSetAttribute(gemm_h_t<1>, cudaFuncAttributeMaxDynamicSharedMemorySize, G_SMEM_BYTES);
    cudaFuncSetAttribute(attn_mma_kernel, cudaFuncAttributeMaxDynamicSharedMemorySize,
                         A_SMEM_BYTES);

    // prep
    {
        int n4 = 4096 * 4096 / 4;
        convert_h_kernel<<<(n4 + 255) / 256, 256>>>((const float4*)hidden, (uint2*)hid_h, n4);
    }
    transpose_h_kernel<<<dim3(4608 / 32, 4096 / 32), dim3(32, 8)>>>(w_qkv, wqkvT_h, 4096, 4608);
    transpose_h_kernel<<<dim3(4096 / 32, 4096 / 32), dim3(32, 8)>>>(w_dense, wdenseT_h, 4096, 4096);

    // 1) QKV gemm with fused bias+rope+pack epilogue
    gemm_h_t<1><<<dim3(4608 / 128, 4096 / 128), 256, G_SMEM_BYTES>>>(
        hid_h, wqkvT_h, b_qkv, nullptr, q_h, k_h, v_h, positions, 4096, 4608, 4096);

    // 2) flash attention: 64-row CTAs, 4 warps, 2 CTAs/SM
    attn_mma_kernel<<<dim3(32, 32, 2), 128, A_SMEM_BYTES>>>(q_h, k_h, v_h, attn_h);

    // 3) dense projection
    gemm_h_t<0><<<dim3(4096 / 128, 4096 / 128), 256, G_SMEM_BYTES>>>(
        attn_h, wdenseT_h, nullptr, out, nullptr, nullptr, nullptr, nullptr, 4096, 4096, 4096);
}

// round 13
// speedup vs baseline: 1.0906x; 1.0906x over previous
#include <cuda_runtime.h>
#include <cuda_fp16.h>
#include <math.h>
#include <stdint.h>

// ---------------- constants ----------------
// B=2, S=2048, H=4096, NH=32, NKV=2, HD=128, ROT=64
// BS=4096 tokens; qkv width 4608 (q:[0,4096) k:[4096,4352) v:[4352,4608))

__device__ __half g_hid_h[(size_t)4096 * 4096];
__device__ __half g_wqkvT_h[(size_t)4608 * 4096];
__device__ __half g_wdenseT_h[(size_t)4096 * 4096];
__device__ __half g_q_h[(size_t)2 * 32 * 2048 * 128];  // [b][h][t][d] rope+scale
__device__ __half g_k_h[(size_t)2 * 2 * 2048 * 128];   // [b][kvh][t][d] rope
__device__ __half g_v_h[(size_t)4096 * 256];           // [tok][dglob]
__device__ __half g_attn_h[(size_t)4096 * 4096];       // [tok][H]

// ---------------- helpers ----------------
__device__ __forceinline__ uint32_t smem_u32(const void* p) {
    uint32_t a;
    asm("{ .reg .u64 t; cvta.to.shared.u64 t, %1; cvt.u32.u64 %0, t; }" : "=r"(a) : "l"(p));
    return a;
}
__device__ __forceinline__ void cp16(uint32_t s, const void* g) {
    asm volatile("cp.async.cg.shared.global [%0], [%1], 16;" :: "r"(s), "l"(g));
}
__device__ __forceinline__ void mma_f16(float* d, const uint32_t* a, const uint32_t* b) {
    asm volatile(
        "mma.sync.aligned.m16n8k16.row.col.f32.f16.f16.f32 "
        "{%0,%1,%2,%3}, {%4,%5,%6,%7}, {%8,%9}, {%0,%1,%2,%3};"
        : "+f"(d[0]), "+f"(d[1]), "+f"(d[2]), "+f"(d[3])
        : "r"(a[0]), "r"(a[1]), "r"(a[2]), "r"(a[3]), "r"(b[0]), "r"(b[1]));
}
__device__ __forceinline__ void ldsm4(uint32_t* r, uint32_t addr) {
    asm volatile("ldmatrix.sync.aligned.m8n8.x4.shared.b16 {%0,%1,%2,%3}, [%4];"
                 : "=r"(r[0]), "=r"(r[1]), "=r"(r[2]), "=r"(r[3]) : "r"(addr));
}
__device__ __forceinline__ void ldsm4t(uint32_t* r, uint32_t addr) {
    asm volatile("ldmatrix.sync.aligned.m8n8.x4.trans.shared.b16 {%0,%1,%2,%3}, [%4];"
                 : "=r"(r[0]), "=r"(r[1]), "=r"(r[2]), "=r"(r[3]) : "r"(addr));
}
__device__ __forceinline__ uint32_t packh2(float x, float y) {
    __half2 h = __floats2half2_rn(x, y);
    return *(uint32_t*)&h;
}

// ---------------- fp16 mma GEMM (ldmatrix, K-chunk 32) — LOCKED R6/R8 config ----
#define GS 3
#define STG_H 10240
#define STG_B (STG_H * 2)                 // 20480 bytes/stage
#define G_SMEM_BYTES (GS * STG_B)         // 61440

template <int MODE>
__global__ __launch_bounds__(256, 2)
void gemm_h_t(const __half* __restrict__ A, const __half* __restrict__ Bt,
              const float* __restrict__ bias, float* __restrict__ C,
              __half* __restrict__ qh, __half* __restrict__ kh, __half* __restrict__ vh,
              const int* __restrict__ positions, int M, int N, int K)
{
    extern __shared__ __half sh[];
    const uint32_t sb = smem_u32(sh);
    const int tid = threadIdx.x;
    const int wid = tid >> 5, lane = tid & 31;
    const int grp = lane >> 2, thr = lane & 3;
    const int wm = wid & 3, wn = wid >> 2;
    const int m0 = blockIdx.y * 128, n0 = blockIdx.x * 128;

    const int row = tid >> 1;
    const int off = (tid & 1) * 16;
    const __half* Ap = A + (size_t)(m0 + row) * K + off;
    const __half* Bp = Bt + (size_t)(n0 + row) * K + off;
    const uint32_t sA = sb + (uint32_t)(row * 40 + off) * 2;
    const uint32_t sB = sA + STG_H;

    auto load_stage = [&](int ch, int st) {
        const uint32_t so = (uint32_t)st * STG_B;
        const __half* a = Ap + ch * 32;
        const __half* b = Bp + ch * 32;
        cp16(sA + so, a);  cp16(sA + so + 16, a + 8);
        cp16(sB + so, b);  cp16(sB + so + 16, b + 8);
        asm volatile("cp.async.commit_group;" ::: "memory");
    };

    float acc[2][8][4];
#pragma unroll
    for (int mt = 0; mt < 2; mt++)
#pragma unroll
        for (int nt = 0; nt < 8; nt++)
#pragma unroll
            for (int j = 0; j < 4; j++) acc[mt][nt][j] = 0.f;

    const int NK = K >> 5;
    load_stage(0, 0);
    load_stage(1, 1);

    const int lrow = lane & 15;
    const int lcol = (lane >> 4) * 16;
    const uint32_t aAddr = sb + (uint32_t)((wm * 32 + lrow) * 40) * 2 + lcol;
    const uint32_t bAddr = sb + 10240 + (uint32_t)((wn * 64 + lrow) * 40) * 2 + lcol;

    int st = 0;
    for (int i = 0; i < NK; i++) {
        asm volatile("cp.async.wait_group %0;" :: "n"(1) : "memory");
        __syncthreads();
        int nxt = i + 2;
        if (nxt < NK) {
            int ns = st + 2; if (ns >= GS) ns -= GS;
            load_stage(nxt, ns);
        } else {
            asm volatile("cp.async.commit_group;" ::: "memory");
        }

        const uint32_t so = (uint32_t)st * STG_B;
#pragma unroll
        for (int kk = 0; kk < 2; kk++) {
            uint32_t a[2][4];
            ldsm4(a[0], aAddr + so + kk * 32);
            ldsm4(a[1], aAddr + so + 16 * 80 + kk * 32);
            uint32_t b[8][2];
#pragma unroll
            for (int ntp = 0; ntp < 4; ntp++) {
                uint32_t tt[4];
                ldsm4(tt, bAddr + so + ntp * (16 * 80) + kk * 32);
                b[2 * ntp][0] = tt[0];  b[2 * ntp][1] = tt[2];
                b[2 * ntp + 1][0] = tt[1];  b[2 * ntp + 1][1] = tt[3];
            }
#pragma unroll
            for (int mt = 0; mt < 2; mt++)
#pragma unroll
                for (int nt = 0; nt < 8; nt++)
                    mma_f16(acc[mt][nt], a[mt], b[nt]);
        }
        st++; if (st == GS) st = 0;
    }

    if (MODE == 0) {
#pragma unroll
        for (int mt = 0; mt < 2; mt++) {
            const int r0 = m0 + wm * 32 + mt * 16 + grp;
#pragma unroll
            for (int nt = 0; nt < 8; nt++) {
                const int col = n0 + wn * 64 + nt * 8 + thr * 2;
                float b0 = 0.f, b1 = 0.f;
                if (bias) { b0 = __ldg(&bias[col]); b1 = __ldg(&bias[col + 1]); }
                *(float2*)&C[(size_t)r0 * N + col] =
                    make_float2(acc[mt][nt][0] + b0, acc[mt][nt][1] + b1);
                *(float2*)&C[(size_t)(r0 + 8) * N + col] =
                    make_float2(acc[mt][nt][2] + b0, acc[mt][nt][3] + b1);
            }
        }
    } else {
        const int head = n0 >> 7;
#pragma unroll
        for (int mt = 0; mt < 2; mt++) {
            const int r0 = m0 + wm * 32 + mt * 16 + grp;
#pragma unroll
            for (int rs = 0; rs < 2; rs++) {
                const int r = r0 + rs * 8;
                const int t = r & 2047, bb = r >> 11;
                const float pos = (float)__ldg(&positions[r]);
#pragma unroll
                for (int nt = 0; nt < 8; nt++) {
                    const int col = n0 + wn * 64 + nt * 8 + thr * 2;
                    float v0 = acc[mt][nt][rs * 2] + __ldg(&bias[col]);
                    float v1 = acc[mt][nt][rs * 2 + 1] + __ldg(&bias[col + 1]);
                    const int d = col & 127;
                    if (head < 34) {
                        if (d < 64) {
                            const int pi = d >> 1;
                            float ang = pos * __expf((float)(-pi) * 0.28782313662425572f);
                            float c, s;
                            __sincosf(ang, &s, &c);
                            float o1 = v0 * c - v1 * s;
                            float o2 = v0 * s + v1 * c;
                            v0 = o1; v1 = o2;
                        }
                        if (head < 32) {
                            const float sc = 0.08838834764831845f;
                            uint32_t p = packh2(v0 * sc, v1 * sc);
                            *(uint32_t*)(qh + ((((size_t)(bb * 32 + head)) * 2048 + t) * 128 + d)) = p;
                        } else {
                            uint32_t p = packh2(v0, v1);
                            *(uint32_t*)(kh + ((((size_t)(bb * 2 + head - 32)) * 2048 + t) * 128 + d)) = p;
                        }
                    } else {
                        uint32_t p = packh2(v0, v1);
                        *(uint32_t*)(vh + ((size_t)r * 256 + (col - 4352))) = p;
                    }
                }
            }
        }
    }
}

// ---------------- prep kernels ----------------
__global__ void convert_h_kernel(const float4* __restrict__ src, uint2* __restrict__ dst, int n4)
{
    int i = blockIdx.x * blockDim.x + threadIdx.x;
    if (i >= n4) return;
    float4 v = src[i];
    uint2 o;
    o.x = packh2(v.x, v.y);
    o.y = packh2(v.z, v.w);
    dst[i] = o;
}

__global__ void transpose_h_kernel(const float* __restrict__ src, __half* __restrict__ dst,
                                   int R, int C)
{
    __shared__ float t[32][33];
    int c0 = blockIdx.x * 32, r0 = blockIdx.y * 32;
    int x = threadIdx.x, y = threadIdx.y;
#pragma unroll
    for (int i = 0; i < 32; i += 8)
        t[y + i][x] = src[(size_t)(r0 + y + i) * C + c0 + x];
    __syncthreads();
#pragma unroll
    for (int i = 0; i < 32; i += 8)
        dst[(size_t)(c0 + y + i) * R + r0 + x] = __float2half(t[x][y + i]);
}

// ---------------- fp16 mma flash attention (R8 shape + 3-buffer KV ring) ------
// smem halves: Qs[128][136], Ks[3][64][136], Vs[3][64][136] (token-major V)
#define AQ_ST 136
#define AK_ST 136
#define KV_BUF_H (64 * AK_ST)                     // 8704 halves per buffer
#define SQ_OFF 0
#define SK_OFF (128 * AQ_ST)                      // 17408
#define SV_OFF (SK_OFF + 3 * KV_BUF_H)            // 43520
#define A_SMEM_HALVES (SV_OFF + 3 * KV_BUF_H)     // 69632
#define A_SMEM_BYTES (A_SMEM_HALVES * 2)          // 139264

__global__ __launch_bounds__(256, 1)
void attn_mma_kernel(const __half* __restrict__ qh, const __half* __restrict__ kh,
                     const __half* __restrict__ vh, __half* __restrict__ out)
{
    extern __shared__ __half sa[];
    const uint32_t sb = smem_u32(sa);
    const int tid = threadIdx.x;
    const int w = tid >> 5, lane = tid & 31;
    const int grp = lane >> 2, thr = lane & 3;
    const int qt = 15 - blockIdx.x;
    const int h = blockIdx.y, b = blockIdx.z;
    const int kvh = h >> 4;

    const __half* Qg = qh + (((size_t)(b * 32 + h)) * 2048 + qt * 128) * 128;
    const __half* Kg = kh + ((size_t)(b * 2 + kvh)) * 2048 * 128;
    const __half* Vg = vh + (size_t)(b * 2048) * 256 + kvh * 128;

    {
        int r = tid >> 1;
        int s0 = (tid & 1) * 8;
        const __half* src = Qg + r * 128 + s0 * 8;
        uint32_t dst = sb + (uint32_t)(SQ_OFF + r * AQ_ST + s0 * 8) * 2;
#pragma unroll
        for (int j = 0; j < 8; j++) cp16(dst + j * 16, src + j * 8);
    }
    auto load_kv = [&](int kt, int buf) {
        int r = tid >> 2;
        int s0 = (tid & 3) * 4;
        {
            const __half* src = Kg + ((size_t)(kt * 64 + r)) * 128 + s0 * 8;
            uint32_t dst = sb + (uint32_t)(SK_OFF + buf * KV_BUF_H + r * AK_ST + s0 * 8) * 2;
#pragma unroll
            for (int j = 0; j < 4; j++) cp16(dst + j * 16, src + j * 8);
        }
        {
            const __half* src = Vg + ((size_t)(kt * 64 + r)) * 256 + s0 * 8;
            uint32_t dst = sb + (uint32_t)(SV_OFF + buf * KV_BUF_H + r * AK_ST + s0 * 8) * 2;
#pragma unroll
            for (int j = 0; j < 4; j++) cp16(dst + j * 16, src + j * 8);
        }
    };

    const int NT = 2 * qt + 2;
    load_kv(0, 0);
    asm volatile("cp.async.commit_group;" ::: "memory");

    float o[16][4];
#pragma unroll
    for (int nt = 0; nt < 16; nt++)
#pragma unroll
        for (int j = 0; j < 4; j++) o[nt][j] = 0.f;
    float m1 = -1e30f, m2 = -1e30f, l1 = 0.f, l2 = 0.f;

    const int qr1 = qt * 128 + w * 16 + grp;
    const int qr2 = qr1 + 8;
    const int wr_max = qt * 128 + w * 16 + 15;

    const int lrow = lane & 15;
    const int lcol = (lane >> 4) * 16;
    const uint32_t qAddr = sb + (uint32_t)(SQ_OFF + (w * 16 + lrow) * AQ_ST) * 2 + lcol;
    const uint32_t kAddr0 = sb + (uint32_t)(SK_OFF + lrow * AK_ST) * 2 + lcol;
    const uint32_t vAddr0 = sb + (uint32_t)(SV_OFF + lrow * AK_ST + (lane >> 4) * 8) * 2;

    int buf = 0;       // kt % 3
    int nbuf = 1;      // (kt+1) % 3
    for (int kt = 0; kt < NT; kt++) {
        if (kt + 1 < NT) load_kv(kt + 1, nbuf);
        asm volatile("cp.async.commit_group;" ::: "memory");
        asm volatile("cp.async.wait_group 1;" ::: "memory");
        __syncthreads();   // single barrier per tile (3-buffer ring removes WAR guard)

        const bool active = (kt * 64 <= wr_max);
        if (active) {
            const uint32_t kA = kAddr0 + (uint32_t)(buf * KV_BUF_H) * 2;
            const uint32_t vA = vAddr0 + (uint32_t)(buf * KV_BUF_H) * 2;

            float sc[8][4];
#pragma unroll
            for (int nt = 0; nt < 8; nt++)
#pragma unroll
                for (int j = 0; j < 4; j++) sc[nt][j] = 0.f;

#pragma unroll
            for (int kk = 0; kk < 8; kk++) {
                uint32_t aq[4];
                ldsm4(aq, qAddr + kk * 32);
#pragma unroll
                for (int ntp = 0; ntp < 4; ntp++) {
                    uint32_t tt[4];
                    ldsm4(tt, kA + ntp * (16 * AK_ST * 2) + kk * 32);
                    uint32_t b0[2] = {tt[0], tt[2]};
                    uint32_t b1[2] = {tt[1], tt[3]};
                    mma_f16(sc[2 * ntp], aq, b0);
                    mma_f16(sc[2 * ntp + 1], aq, b1);
                }
            }

            if (kt * 64 + 63 > qt * 128 + w * 16) {
#pragma unroll
                for (int nt = 0; nt < 8; nt++) {
                    int c0 = kt * 64 + nt * 8 + thr * 2;
                    if (c0 > qr1) sc[nt][0] = -1e30f;
                    if (c0 + 1 > qr1) sc[nt][1] = -1e30f;
                    if (c0 > qr2) sc[nt][2] = -1e30f;
                    if (c0 + 1 > qr2) sc[nt][3] = -1e30f;
                }
            }

            float rm1 = -1e30f, rm2 = -1e30f;
#pragma unroll
            for (int nt = 0; nt < 8; nt++) {
                rm1 = fmaxf(rm1, fmaxf(sc[nt][0], sc[nt][1]));
                rm2 = fmaxf(rm2, fmaxf(sc[nt][2], sc[nt][3]));
            }
            rm1 = fmaxf(rm1, __shfl_xor_sync(0xffffffffu, rm1, 1));
            rm1 = fmaxf(rm1, __shfl_xor_sync(0xffffffffu, rm1, 2));
            rm2 = fmaxf(rm2, __shfl_xor_sync(0xffffffffu, rm2, 1));
            rm2 = fmaxf(rm2, __shfl_xor_sync(0xffffffffu, rm2, 2));

            float mn1 = fmaxf(m1, rm1), mn2 = fmaxf(m2, rm2);
            float f1 = __expf(m1 - mn1), f2 = __expf(m2 - mn2);
            m1 = mn1; m2 = mn2;

            uint32_t pf[8][2];
            float s1 = 0.f, s2 = 0.f;
#pragma unroll
            for (int nt = 0; nt < 8; nt++) {
                float e0 = __expf(sc[nt][0] - mn1);
                float e1 = __expf(sc[nt][1] - mn1);
                float e2 = __expf(sc[nt][2] - mn2);
                float e3 = __expf(sc[nt][3] - mn2);
                s1 += e0 + e1; s2 += e2 + e3;
                pf[nt][0] = packh2(e0, e1);
                pf[nt][1] = packh2(e2, e3);
            }
            l1 = l1 * f1 + s1;
            l2 = l2 * f2 + s2;

#pragma unroll
            for (int nt = 0; nt < 16; nt++) {
                o[nt][0] *= f1; o[nt][1] *= f1;
                o[nt][2] *= f2; o[nt][3] *= f2;
            }

#pragma unroll
            for (int kk = 0; kk < 4; kk++) {
                uint32_t ap[4] = {pf[2 * kk][0], pf[2 * kk][1],
                                  pf[2 * kk + 1][0], pf[2 * kk + 1][1]};
                const uint32_t vk = vA + (uint32_t)(kk * 16 * AK_ST) * 2;
#pragma unroll
                for (int ntdp = 0; ntdp < 8; ntdp++) {
                    uint32_t tt[4];
                    ldsm4t(tt, vk + ntdp * 32);
                    uint32_t b0[2] = {tt[0], tt[1]};
                    uint32_t b1[2] = {tt[2], tt[3]};
                    mma_f16(o[2 * ntdp], ap, b0);
                    mma_f16(o[2 * ntdp + 1], ap, b1);
                }
            }
        }
        buf = nbuf;
        nbuf++; if (nbuf == 3) nbuf = 0;
    }

    l1 += __shfl_xor_sync(0xffffffffu, l1, 1);
    l1 += __shfl_xor_sync(0xffffffffu, l1, 2);
    l2 += __shfl_xor_sync(0xffffffffu, l2, 1);
    l2 += __shfl_xor_sync(0xffffffffu, l2, 2);
    float inv1 = 1.f / l1, inv2 = 1.f / l2;

    const int row1 = b * 2048 + qr1;
    const int row2 = b * 2048 + qr2;
#pragma unroll
    for (int ntd = 0; ntd < 16; ntd++) {
        int col = h * 128 + ntd * 8 + thr * 2;
        *(uint32_t*)(out + (size_t)row1 * 4096 + col) = packh2(o[ntd][0] * inv1, o[ntd][1] * inv1);
        *(uint32_t*)(out + (size_t)row2 * 4096 + col) = packh2(o[ntd][2] * inv2, o[ntd][3] * inv2);
    }
}

// ---------------- launch ----------------
extern "C" void kernel_launch(void* const* d_in, const int* in_sizes, int n_in,
                              void* d_out, int out_size)
{
    const float* hidden    = (const float*)d_in[0];
    const float* w_qkv     = (const float*)d_in[1];
    const float* b_qkv     = (const float*)d_in[2];
    const float* w_dense   = (const float*)d_in[3];
    const int*   positions = (const int*)d_in[4];
    float* out = (float*)d_out;

    __half *hid_h, *wqkvT_h, *wdenseT_h, *q_h, *k_h, *v_h, *attn_h;
    cudaGetSymbolAddress((void**)&hid_h, g_hid_h);
    cudaGetSymbolAddress((void**)&wqkvT_h, g_wqkvT_h);
    cudaGetSymbolAddress((void**)&wdenseT_h, g_wdenseT_h);
    cudaGetSymbolAddress((void**)&q_h, g_q_h);
    cudaGetSymbolAddress((void**)&k_h, g_k_h);
    cudaGetSymbolAddress((void**)&v_h, g_v_h);
    cudaGetSymbolAddress((void**)&attn_h, g_attn_h);

    cudaFuncSetAttribute(gemm_h_t<0>, cudaFuncAttributeMaxDynamicSharedMemorySize, G_SMEM_BYTES);
    cudaFuncSetAttribute(gemm_h_t<1>, cudaFuncAttributeMaxDynamicSharedMemorySize, G_SMEM_BYTES);
    cudaFuncSetAttribute(attn_mma_kernel, cudaFuncAttributeMaxDynamicSharedMemorySize,
                         A_SMEM_BYTES);

    // prep
    {
        int n4 = 4096 * 4096 / 4;
        convert_h_kernel<<<(n4 + 255) / 256, 256>>>((const float4*)hidden, (uint2*)hid_h, n4);
    }
    transpose_h_kernel<<<dim3(4608 / 32, 4096 / 32), dim3(32, 8)>>>(w_qkv, wqkvT_h, 4096, 4608);
    transpose_h_kernel<<<dim3(4096 / 32, 4096 / 32), dim3(32, 8)>>>(w_dense, wdenseT_h, 4096, 4096);

    // 1) QKV gemm with fused bias+rope+pack epilogue
    gemm_h_t<1><<<dim3(4608 / 128, 4096 / 128), 256, G_SMEM_BYTES>>>(
        hid_h, wqkvT_h, b_qkv, nullptr, q_h, k_h, v_h, positions, 4096, 4608, 4096);

    // 2) flash attention (128-row CTAs, 3-buffer KV ring, trans-V)
    attn_mma_kernel<<<dim3(16, 32, 2), 256, A_SMEM_BYTES>>>(q_h, k_h, v_h, attn_h);

    // 3) dense projection
    gemm_h_t<0><<<dim3(4096 / 128, 4096 / 128), 256, G_SMEM_BYTES>>>(
        attn_h, wdenseT_h, nullptr, out, nullptr, nullptr, nullptr, nullptr, 4096, 4096, 4096);
}